// round 15
// baseline (speedup 1.0000x reference)
#include <cuda_runtime.h>
#include <cuda_fp16.h>
#include <math.h>
#include <stdint.h>

#define DIM   4096
#define S_LEN 2048
#define HD    128
#define NH    32
#define NKV   8
#define KVDIM (NKV*HD)   // 1024
#define KTOT  4096
#define NK    (KTOT/32)  // 128
#define NQKV  (DIM + 2*KVDIM)   // 6144
#define GEMM_GRID 296           // 2 CTAs x 148 SMs

// ======================= scratch globals ===================================
__device__ __half g_xhi [S_LEN * DIM];
__device__ __half g_xlo [S_LEN * DIM];
__device__ __half g_wqkvt[NQKV * KTOT];   // single fp16: wq^T | wk^T | wv^T
__device__ __half g_wot  [DIM * KTOT];
__device__ __half g_qhi [S_LEN * DIM];
__device__ __half g_qlo [S_LEN * DIM];
__device__ __half g_k   [S_LEN * KVDIM];
__device__ __half g_v   [S_LEN * KVDIM];
__device__ __half g_atthi[S_LEN * DIM];
__device__ __half g_attlo[S_LEN * DIM];

// ======================= asm helpers (sm_100-safe) =========================
__device__ __forceinline__ uint32_t smem_u32(const void* p) {
    uint32_t a;
    asm("{ .reg .u64 t; cvta.to.shared.u64 t, %1; cvt.u32.u64 %0, t; }"
        : "=r"(a) : "l"(p));
    return a;
}
#define CP_ASYNC16(dst, src) \
    asm volatile("cp.async.cg.shared.global [%0], [%1], 16;" :: "r"(dst), "l"(src))
#define CP_COMMIT()  asm volatile("cp.async.commit_group;" ::: "memory")
#define CP_WAIT0()   asm volatile("cp.async.wait_group 0;"  ::: "memory")
#define CP_WAIT1()   asm volatile("cp.async.wait_group 1;"  ::: "memory")

__device__ __forceinline__ void ldsm_x4(uint32_t* r, uint32_t addr) {
    asm volatile("ldmatrix.sync.aligned.m8n8.x4.shared.b16 {%0,%1,%2,%3}, [%4];"
                 : "=r"(r[0]), "=r"(r[1]), "=r"(r[2]), "=r"(r[3]) : "r"(addr));
}
__device__ __forceinline__ void ldsm_x4t(uint32_t* r, uint32_t addr) {
    asm volatile("ldmatrix.sync.aligned.m8n8.x4.trans.shared.b16 {%0,%1,%2,%3}, [%4];"
                 : "=r"(r[0]), "=r"(r[1]), "=r"(r[2]), "=r"(r[3]) : "r"(addr));
}
__device__ __forceinline__ void mma16816h(float* c, const uint32_t* a, const uint32_t* b) {
    asm volatile("mma.sync.aligned.m16n8k16.row.col.f32.f16.f16.f32 "
                 "{%0,%1,%2,%3}, {%4,%5,%6,%7}, {%8,%9}, {%0,%1,%2,%3};"
                 : "+f"(c[0]), "+f"(c[1]), "+f"(c[2]), "+f"(c[3])
                 : "r"(a[0]), "r"(a[1]), "r"(a[2]), "r"(a[3]), "r"(b[0]), "r"(b[1]));
}
__device__ __forceinline__ uint32_t pack_half(float a, float b) {
    __half2 h = __floats2half2_rn(a, b);
    return *(uint32_t*)&h;
}

// ======================= conversion kernels ================================
__global__ __launch_bounds__(256)
void split_kernel(const float* __restrict__ in, __half* __restrict__ hi,
                  __half* __restrict__ lo, int n4)
{
    int i = blockIdx.x * blockDim.x + threadIdx.x;
    if (i >= n4) return;
    float4 v = ((const float4*)in)[i];
    __half h0 = __float2half_rn(v.x), h1 = __float2half_rn(v.y);
    __half h2 = __float2half_rn(v.z), h3 = __float2half_rn(v.w);
    __half l0 = __float2half_rn(v.x - __half2float(h0));
    __half l1 = __float2half_rn(v.y - __half2float(h1));
    __half l2 = __float2half_rn(v.z - __half2float(h2));
    __half l3 = __float2half_rn(v.w - __half2float(h3));
    ushort4 hv = make_ushort4(*(unsigned short*)&h0, *(unsigned short*)&h1,
                              *(unsigned short*)&h2, *(unsigned short*)&h3);
    ushort4 lv = make_ushort4(*(unsigned short*)&l0, *(unsigned short*)&l1,
                              *(unsigned short*)&l2, *(unsigned short*)&l3);
    ((ushort4*)hi)[i] = hv;
    ((ushort4*)lo)[i] = lv;
}

// W[K][N] fp32 -> T[N][K] single fp16 (transpose)
__global__ __launch_bounds__(256)
void transpose_half_kernel(const float* __restrict__ W, __half* __restrict__ T,
                           int K, int N)
{
    __shared__ float t[32][33];
    int n0 = blockIdx.x * 32, k0 = blockIdx.y * 32;
    int tx = threadIdx.x & 31, ty = threadIdx.x >> 5;
#pragma unroll
    for (int i = 0; i < 4; i++)
        t[ty + i * 8][tx] = W[(size_t)(k0 + ty + i * 8) * N + n0 + tx];
    __syncthreads();
#pragma unroll
    for (int i = 0; i < 4; i++)
        T[(size_t)(n0 + ty + i * 8) * K + k0 + tx] = __float2half_rn(t[tx][ty + i * 8]);
}

// ======================= mma.sync GEMM (fp16 2-product, persistent) ========
// C = (Ahi+Alo)[M,K] @ B[N,K]^T, fp32 acc. BM=BN=128, BK=32, 3-stage
// cp.async pipeline (wait_group 1), 256 thr, warps 4x2, warp tile 32x64.
// Persistent: grid=296, each CTA loops over tiles (kills wave quantization).
// MODE 0: fp32 C out (O projection).  MODE 1: fused QKV, per-tile dispatch.
#define GSTRIDE  40
#define GS_MAT   (128 * GSTRIDE * 2)        // 10240 B
#define GS_STAGE (3 * GS_MAT)               // 30720 B: Ahi|Alo|B
#define GSTAGES  3
#define GEMM_SMEM_BYTES (GSTAGES * GS_STAGE)  // 92160

template<int MODE>
__global__ __launch_bounds__(256, 2)
void gemm_mma(const __half* __restrict__ Ahi, const __half* __restrict__ Alo,
              const __half* __restrict__ B,
              float* __restrict__ C,
              const float* __restrict__ fcos, const float* __restrict__ fsin,
              int gridX, int numTiles)
{
    extern __shared__ char smem[];
    const uint32_t sbase = smem_u32(smem);
    const int tid  = threadIdx.x;
    const int lane = tid & 31;
    const int wid  = tid >> 5;
    const int wm   = wid & 3;
    const int wn   = wid >> 2;

    const int am  = (lane & 7) + ((lane >> 3) & 1) * 8;
    const int ak  = (lane >> 4) * 8;
    const int bn4 = (lane & 7) + ((lane >> 4) & 1) * 8;
    const int bk4 = ((lane >> 3) & 1) * 8;
    const int qrow = lane >> 2;
    const int qcol = (lane & 3) * 2;
    const float osc = 0.08838834764831844f;          // 1/sqrt(128), Q only

    for (int tile = blockIdx.x; tile < numTiles; tile += GEMM_GRID) {
        const int rowBase = (tile / gridX) * 128;
        const int colBase = (tile % gridX) * 128;

        auto prefetch = [&](int slot, int k0) {
            uint32_t st = sbase + (uint32_t)slot * GS_STAGE;
#pragma unroll
            for (int c = 0; c < 2; c++) {
                int ch  = tid + c * 256;          // 0..511
                int row = ch >> 2;                // 0..127
                int kc  = (ch & 3) * 8;           // 0,8,16,24
                uint32_t sm = (uint32_t)(row * GSTRIDE + kc) * 2;
                size_t ga = (size_t)(rowBase + row) * KTOT + k0 + kc;
                size_t gb = (size_t)(colBase + row) * KTOT + k0 + kc;
                CP_ASYNC16(st + 0 * GS_MAT + sm, Ahi + ga);
                CP_ASYNC16(st + 1 * GS_MAT + sm, Alo + ga);
                CP_ASYNC16(st + 2 * GS_MAT + sm, B   + gb);
            }
            CP_COMMIT();
        };

        float acc[2][8][4];
#pragma unroll
        for (int mi = 0; mi < 2; mi++)
#pragma unroll
            for (int ni = 0; ni < 8; ni++)
#pragma unroll
                for (int r = 0; r < 4; r++) acc[mi][ni][r] = 0.0f;

        prefetch(0, 0);
        prefetch(1, 32);

        int slot = 0;
        for (int i = 0; i < NK; i++) {
            CP_WAIT1();
            __syncthreads();
            if (i + 2 < NK) prefetch((i + 2) % 3, (i + 2) * 32);
            else            CP_COMMIT();    // keep outstanding-group invariant

            const uint32_t st   = sbase + (uint32_t)slot * GS_STAGE;
            const uint32_t aHiB = st, aLoB = st + GS_MAT, bB = st + 2 * GS_MAT;
            slot = (slot + 1 == 3) ? 0 : slot + 1;

#pragma unroll
            for (int ks = 0; ks < 32; ks += 16) {
                uint32_t aHi[2][4], aLo[2][4];
#pragma unroll
                for (int mi = 0; mi < 2; mi++) {
                    uint32_t off = (uint32_t)((wm * 32 + mi * 16 + am) * GSTRIDE + ks + ak) * 2;
                    ldsm_x4(aHi[mi], aHiB + off);
                    ldsm_x4(aLo[mi], aLoB + off);
                }
#pragma unroll
                for (int ni2 = 0; ni2 < 4; ni2++) {
                    uint32_t boff = (uint32_t)((wn * 64 + ni2 * 16 + bn4) * GSTRIDE + ks + bk4) * 2;
                    uint32_t bh[4];
                    ldsm_x4(bh, bB + boff);
#pragma unroll
                    for (int mi = 0; mi < 2; mi++) {
                        mma16816h(acc[mi][2 * ni2],     aHi[mi], bh);
                        mma16816h(acc[mi][2 * ni2 + 1], aHi[mi], bh + 2);
                        mma16816h(acc[mi][2 * ni2],     aLo[mi], bh);
                        mma16816h(acc[mi][2 * ni2 + 1], aLo[mi], bh + 2);
                    }
                }
            }
        }

        // ---- epilogue ----
        int region = 0, Nout = DIM, colOff = colBase;    // MODE 1 dispatch
        if (MODE == 1) {
            if (colBase < DIM)              { region = 0; Nout = DIM;   colOff = colBase; }
            else if (colBase < DIM + KVDIM) { region = 1; Nout = KVDIM; colOff = colBase - DIM; }
            else                            { region = 2; Nout = KVDIM; colOff = colBase - DIM - KVDIM; }
        }

#pragma unroll
        for (int mi = 0; mi < 2; mi++) {
#pragma unroll
            for (int half = 0; half < 2; half++) {
                int r = rowBase + wm * 32 + mi * 16 + qrow + half * 8;
#pragma unroll
                for (int ni = 0; ni < 8; ni++) {
                    int n_g = colOff + wn * 64 + ni * 8 + qcol;
                    float c0 = acc[mi][ni][half * 2];
                    float c1 = acc[mi][ni][half * 2 + 1];
                    if (MODE == 0) {
                        *(float2*)&C[(size_t)r * DIM + n_g] = make_float2(c0, c1);
                    } else {
                        float ox = c0, oy = c1;
                        if (region < 2) {                 // rope for Q and K
                            int d = (n_g & (HD - 1)) >> 1;
                            float fc = fcos[r * (HD / 2) + d];
                            float fs = fsin[r * (HD / 2) + d];
                            ox = c0 * fc - c1 * fs;
                            oy = c0 * fs + c1 * fc;
                        }
                        size_t o = (size_t)r * Nout + n_g;
                        if (region == 0) {                // Q: scale + split
                            ox *= osc; oy *= osc;
                            __half h0 = __float2half_rn(ox);
                            __half h1 = __float2half_rn(oy);
                            *(uint32_t*)&g_qhi[o] = pack_half(__half2float(h0), __half2float(h1));
                            *(uint32_t*)&g_qlo[o] = pack_half(ox - __half2float(h0),
                                                              oy - __half2float(h1));
                        } else if (region == 1) {         // K: single fp16
                            *(uint32_t*)&g_k[o] = pack_half(ox, oy);
                        } else {                          // V: single fp16
                            *(uint32_t*)&g_v[o] = pack_half(ox, oy);
                        }
                    }
                }
            }
        }
        __syncthreads();   // all smem reads done before next tile's prefetch
    }
}

// ======================= flash attention (fp16 2-product) ==================
// BM=64 q rows (4 warps x m16), BN=64 keys/tile, 128 threads, 2 CTAs/SM.
#define FPAD 136
#define FQ_BYTES   (64 * FPAD * 2)         // 17408 (per Q split-matrix)
#define FT_BYTES   (64 * FPAD * 2)         // 17408
#define FKV_BYTES  (2 * FT_BYTES)          // 34816: K | V
#define FLASH_SMEM (2 * FQ_BYTES + 2 * FKV_BYTES)   // 104448

__global__ __launch_bounds__(128, 2)
void flash_mma(const __half* __restrict__ qhi, const __half* __restrict__ qlo,
               const __half* __restrict__ k,  const __half* __restrict__ v,
               __half* __restrict__ atthi, __half* __restrict__ attlo)
{
    extern __shared__ char smem[];
    const uint32_t sbase = smem_u32(smem);
    const int tid  = threadIdx.x;
    const int lane = tid & 31;
    const int w    = tid >> 5;            // 4 warps: rows w*16..w*16+15
    const int qt   = gridDim.x - 1 - blockIdx.x;   // big tiles first
    const int head = blockIdx.y;
    const int kvh  = head >> 2;
    const int qbase = qt * 64;
    const int ktmax = qt;

    const uint32_t QHI = sbase;
    const uint32_t QLO = sbase + FQ_BYTES;
    const uint32_t KVB = sbase + 2 * FQ_BYTES;

#pragma unroll
    for (int t = 0; t < 16; t++) {
        int c = tid + t * 128;            // 0..2047
        int arr = c >> 10;                // 0=hi, 1=lo
        int rem = c & 1023;
        int row = rem >> 4;               // 0..63
        int ch  = rem & 15;
        const __half* src = arr ? qlo : qhi;
        uint32_t dst = (arr ? QLO : QHI) + (uint32_t)(row * FPAD + ch * 8) * 2;
        CP_ASYNC16(dst, src + (size_t)(qbase + row) * DIM + head * HD + ch * 8);
    }
    auto load_kv = [&](int buf, int kt) {
        const int kbase = kt * 64;
        uint32_t base = KVB + (uint32_t)buf * FKV_BYTES;
#pragma unroll
        for (int t = 0; t < 16; t++) {
            int c = tid + t * 128;        // 0..2047
            int arr = c >> 10;            // 0=K, 1=V
            int rem = c & 1023;
            int row = rem >> 4;
            int ch  = rem & 15;
            const __half* src = arr ? v : k;
            uint32_t dst = base + (uint32_t)arr * FT_BYTES + (uint32_t)(row * FPAD + ch * 8) * 2;
            CP_ASYNC16(dst, src + (size_t)(kbase + row) * KVDIM + kvh * HD + ch * 8);
        }
        CP_COMMIT();
    };
    load_kv(0, 0);   // one commit covering Q + tile 0

    const int am  = (lane & 7) + ((lane >> 3) & 1) * 8;
    const int ak  = (lane >> 4) * 8;
    const int kn4 = (lane & 7) + ((lane >> 4) & 1) * 8;
    const int kk4 = ((lane >> 3) & 1) * 8;
    const int vrow = ((lane >> 3) & 1) * 8 + (lane & 7);
    const int vcol = ((lane >> 4) & 1) * 8;
    const int qrow = lane >> 2;
    const int qcol = (lane & 3) * 2;

    float O[16][4];
#pragma unroll
    for (int ni = 0; ni < 16; ni++)
#pragma unroll
        for (int r = 0; r < 4; r++) O[ni][r] = 0.0f;
    float m0 = -1e30f, m1 = -1e30f, l0 = 0.0f, l1 = 0.0f;

    for (int kt = 0; kt <= ktmax; kt++) {
        CP_WAIT0();
        __syncthreads();
        if (kt + 1 <= ktmax) load_kv((kt + 1) & 1, kt + 1);

        const uint32_t base = KVB + (uint32_t)(kt & 1) * FKV_BYTES;
        const uint32_t KB = base, VB = base + FT_BYTES;

        // ---- S = (Qhi+Qlo) K^T ----
        float S[8][4];
#pragma unroll
        for (int j = 0; j < 8; j++)
#pragma unroll
            for (int r = 0; r < 4; r++) S[j][r] = 0.0f;

#pragma unroll
        for (int ks = 0; ks < 8; ks++) {
            uint32_t qh[4], ql[4];
            uint32_t qoff = (uint32_t)((w * 16 + am) * FPAD + ks * 16 + ak) * 2;
            ldsm_x4(qh, QHI + qoff);
            ldsm_x4(ql, QLO + qoff);
#pragma unroll
            for (int jp = 0; jp < 4; jp++) {
                uint32_t koff = (uint32_t)((jp * 16 + kn4) * FPAD + ks * 16 + kk4) * 2;
                uint32_t kh[4];
                ldsm_x4(kh, KB + koff);
                mma16816h(S[2 * jp],     qh, kh);
                mma16816h(S[2 * jp + 1], qh, kh + 2);
                mma16816h(S[2 * jp],     ql, kh);
                mma16816h(S[2 * jp + 1], ql, kh + 2);
            }
        }

        if (kt == qt) {                    // diagonal tile only
            const int kbase = kt * 64;
            int gq0 = qbase + w * 16 + qrow;
            int gq1 = gq0 + 8;
#pragma unroll
            for (int j = 0; j < 8; j++) {
                int gk = kbase + j * 8 + qcol;
                if (gk     > gq0) S[j][0] = -1e30f;
                if (gk + 1 > gq0) S[j][1] = -1e30f;
                if (gk     > gq1) S[j][2] = -1e30f;
                if (gk + 1 > gq1) S[j][3] = -1e30f;
            }
        }

        float mx0 = -1e30f, mx1 = -1e30f;
#pragma unroll
        for (int j = 0; j < 8; j++) {
            mx0 = fmaxf(mx0, fmaxf(S[j][0], S[j][1]));
            mx1 = fmaxf(mx1, fmaxf(S[j][2], S[j][3]));
        }
        mx0 = fmaxf(mx0, __shfl_xor_sync(0xffffffffu, mx0, 1));
        mx0 = fmaxf(mx0, __shfl_xor_sync(0xffffffffu, mx0, 2));
        mx1 = fmaxf(mx1, __shfl_xor_sync(0xffffffffu, mx1, 1));
        mx1 = fmaxf(mx1, __shfl_xor_sync(0xffffffffu, mx1, 2));

        float m0n = fmaxf(m0, mx0), m1n = fmaxf(m1, mx1);
        float a0 = __expf(m0 - m0n), a1 = __expf(m1 - m1n);
        float s0 = 0.0f, s1 = 0.0f;
#pragma unroll
        for (int j = 0; j < 8; j++) {
            S[j][0] = __expf(S[j][0] - m0n);
            S[j][1] = __expf(S[j][1] - m0n);
            S[j][2] = __expf(S[j][2] - m1n);
            S[j][3] = __expf(S[j][3] - m1n);
            s0 += S[j][0] + S[j][1];
            s1 += S[j][2] + S[j][3];
        }
        s0 += __shfl_xor_sync(0xffffffffu, s0, 1);
        s0 += __shfl_xor_sync(0xffffffffu, s0, 2);
        s1 += __shfl_xor_sync(0xffffffffu, s1, 1);
        s1 += __shfl_xor_sync(0xffffffffu, s1, 2);
        l0 = l0 * a0 + s0;  m0 = m0n;
        l1 = l1 * a1 + s1;  m1 = m1n;
#pragma unroll
        for (int ni = 0; ni < 16; ni++) {
            O[ni][0] *= a0; O[ni][1] *= a0;
            O[ni][2] *= a1; O[ni][3] *= a1;
        }

        // ---- O += (Phi+Plo) V ----
#pragma unroll
        for (int kt2 = 0; kt2 < 4; kt2++) {
            uint32_t ph[4], pl[4];
#pragma unroll
            for (int half = 0; half < 2; half++) {
                float p0 = S[2 * kt2 + half][0], p1 = S[2 * kt2 + half][1];
                float p2 = S[2 * kt2 + half][2], p3 = S[2 * kt2 + half][3];
                __half q0 = __float2half_rn(p0), q1 = __float2half_rn(p1);
                __half q2 = __float2half_rn(p2), q3 = __float2half_rn(p3);
                float h0 = __half2float(q0), h1 = __half2float(q1);
                float h2 = __half2float(q2), h3 = __half2float(q3);
                ph[half * 2 + 0] = pack_half(h0, h1);
                ph[half * 2 + 1] = pack_half(h2, h3);
                pl[half * 2 + 0] = pack_half(p0 - h0, p1 - h1);
                pl[half * 2 + 1] = pack_half(p2 - h2, p3 - h3);
            }
#pragma unroll
            for (int nip = 0; nip < 8; nip++) {
                uint32_t voff = (uint32_t)((kt2 * 16 + vrow) * FPAD + nip * 16 + vcol) * 2;
                uint32_t vh[4];
                ldsm_x4t(vh, VB + voff);
                mma16816h(O[2 * nip],     ph, vh);
                mma16816h(O[2 * nip + 1], ph, vh + 2);
                mma16816h(O[2 * nip],     pl, vh);
                mma16816h(O[2 * nip + 1], pl, vh + 2);
            }
        }
    }

    float inv0 = 1.0f / l0, inv1 = 1.0f / l1;
    int gq0 = qbase + w * 16 + qrow;
    int gq1 = gq0 + 8;
#pragma unroll
    for (int ni = 0; ni < 16; ni++) {
        int col = head * HD + ni * 8 + qcol;
        float o0 = O[ni][0] * inv0, o1 = O[ni][1] * inv0;
        float o2 = O[ni][2] * inv1, o3 = O[ni][3] * inv1;
        __half e0 = __float2half_rn(o0), e1 = __float2half_rn(o1);
        __half e2 = __float2half_rn(o2), e3 = __float2half_rn(o3);
        float h0 = __half2float(e0), h1 = __half2float(e1);
        float h2 = __half2float(e2), h3 = __half2float(e3);
        size_t p0 = (size_t)gq0 * DIM + col;
        size_t p1 = (size_t)gq1 * DIM + col;
        *(uint32_t*)&atthi[p0] = pack_half(h0, h1);
        *(uint32_t*)&attlo[p0] = pack_half(o0 - h0, o1 - h1);
        *(uint32_t*)&atthi[p1] = pack_half(h2, h3);
        *(uint32_t*)&attlo[p1] = pack_half(o2 - h2, o3 - h3);
    }
}

// ======================= launch ============================================
extern "C" void kernel_launch(void* const* d_in, const int* in_sizes, int n_in,
                              void* d_out, int out_size)
{
    const float* x    = (const float*)d_in[0];
    const float* wq   = (const float*)d_in[1];
    const float* wk   = (const float*)d_in[2];
    const float* wv   = (const float*)d_in[3];
    const float* wo   = (const float*)d_in[4];
    const float* fcos = (const float*)d_in[5];
    const float* fsin = (const float*)d_in[6];
    float* out = (float*)d_out;

    __half *xhi, *xlo, *wqkvt, *wot, *qhi, *qlo, *kk, *vv, *atthi, *attlo;
    cudaGetSymbolAddress((void**)&xhi,   g_xhi);
    cudaGetSymbolAddress((void**)&xlo,   g_xlo);
    cudaGetSymbolAddress((void**)&wqkvt, g_wqkvt);
    cudaGetSymbolAddress((void**)&wot,   g_wot);
    cudaGetSymbolAddress((void**)&qhi,   g_qhi);
    cudaGetSymbolAddress((void**)&qlo,   g_qlo);
    cudaGetSymbolAddress((void**)&kk,    g_k);
    cudaGetSymbolAddress((void**)&vv,    g_v);
    cudaGetSymbolAddress((void**)&atthi, g_atthi);
    cudaGetSymbolAddress((void**)&attlo, g_attlo);

    cudaFuncSetAttribute(gemm_mma<0>,
                         cudaFuncAttributeMaxDynamicSharedMemorySize, GEMM_SMEM_BYTES);
    cudaFuncSetAttribute(gemm_mma<1>,
                         cudaFuncAttributeMaxDynamicSharedMemorySize, GEMM_SMEM_BYTES);
    cudaFuncSetAttribute(flash_mma,
                         cudaFuncAttributeMaxDynamicSharedMemorySize, FLASH_SMEM);

    int n4x = S_LEN * DIM / 4;

    split_kernel<<<(n4x + 255) / 256, 256>>>(x, xhi, xlo, n4x);
    transpose_half_kernel<<<dim3(DIM / 32,   DIM / 32), 256>>>(wq, wqkvt, KTOT, DIM);
    transpose_half_kernel<<<dim3(KVDIM / 32, DIM / 32), 256>>>(
        wk, wqkvt + (size_t)DIM * KTOT, KTOT, KVDIM);
    transpose_half_kernel<<<dim3(KVDIM / 32, DIM / 32), 256>>>(
        wv, wqkvt + (size_t)(DIM + KVDIM) * KTOT, KTOT, KVDIM);
    transpose_half_kernel<<<dim3(DIM / 32,   DIM / 32), 256>>>(wo, wot, KTOT, DIM);

    // persistent fused QKV projection: 768 tiles over 296 CTAs
    gemm_mma<1><<<GEMM_GRID, 256, GEMM_SMEM_BYTES>>>(
        xhi, xlo, wqkvt, nullptr, fcos, fsin,
        NQKV / 128, (NQKV / 128) * (S_LEN / 128));

    flash_mma<<<dim3(S_LEN / 64, NH), 128, FLASH_SMEM>>>(
        qhi, qlo, kk, vv, atthi, attlo);

    // persistent O projection: 512 tiles over 296 CTAs
    gemm_mma<0><<<GEMM_GRID, 256, GEMM_SMEM_BYTES>>>(
        atthi, attlo, wot, out, nullptr, nullptr,
        DIM / 128, (DIM / 128) * (S_LEN / 128));
}

// round 16
// speedup vs baseline: 1.2172x; 1.2172x over previous
#include <cuda_runtime.h>
#include <cuda_fp16.h>
#include <math.h>
#include <stdint.h>

#define DIM   4096
#define S_LEN 2048
#define HD    128
#define NH    32
#define NKV   8
#define KVDIM (NKV*HD)   // 1024
#define KTOT  4096
#define NK    (KTOT/32)  // 128
#define NQKV  (DIM + 2*KVDIM)   // 6144

// ======================= scratch globals ===================================
__device__ __half g_xhi [S_LEN * DIM];
__device__ __half g_xlo [S_LEN * DIM];
__device__ __half g_wqkvt[NQKV * KTOT];   // single fp16: wq^T | wk^T | wv^T
__device__ __half g_wot  [DIM * KTOT];
__device__ __half g_qhi [S_LEN * DIM];
__device__ __half g_qlo [S_LEN * DIM];
__device__ __half g_k   [S_LEN * KVDIM];
__device__ __half g_v   [S_LEN * KVDIM];
__device__ __half g_atthi[S_LEN * DIM];
__device__ __half g_attlo[S_LEN * DIM];

// ======================= asm helpers (sm_100-safe) =========================
__device__ __forceinline__ uint32_t smem_u32(const void* p) {
    uint32_t a;
    asm("{ .reg .u64 t; cvta.to.shared.u64 t, %1; cvt.u32.u64 %0, t; }"
        : "=r"(a) : "l"(p));
    return a;
}
#define CP_ASYNC16(dst, src) \
    asm volatile("cp.async.cg.shared.global [%0], [%1], 16;" :: "r"(dst), "l"(src))
#define CP_COMMIT()  asm volatile("cp.async.commit_group;" ::: "memory")
#define CP_WAIT0()   asm volatile("cp.async.wait_group 0;"  ::: "memory")
#define CP_WAIT1()   asm volatile("cp.async.wait_group 1;"  ::: "memory")

__device__ __forceinline__ void ldsm_x4(uint32_t* r, uint32_t addr) {
    asm volatile("ldmatrix.sync.aligned.m8n8.x4.shared.b16 {%0,%1,%2,%3}, [%4];"
                 : "=r"(r[0]), "=r"(r[1]), "=r"(r[2]), "=r"(r[3]) : "r"(addr));
}
__device__ __forceinline__ void ldsm_x4t(uint32_t* r, uint32_t addr) {
    asm volatile("ldmatrix.sync.aligned.m8n8.x4.trans.shared.b16 {%0,%1,%2,%3}, [%4];"
                 : "=r"(r[0]), "=r"(r[1]), "=r"(r[2]), "=r"(r[3]) : "r"(addr));
}
__device__ __forceinline__ void mma16816h(float* c, const uint32_t* a, const uint32_t* b) {
    asm volatile("mma.sync.aligned.m16n8k16.row.col.f32.f16.f16.f32 "
                 "{%0,%1,%2,%3}, {%4,%5,%6,%7}, {%8,%9}, {%0,%1,%2,%3};"
                 : "+f"(c[0]), "+f"(c[1]), "+f"(c[2]), "+f"(c[3])
                 : "r"(a[0]), "r"(a[1]), "r"(a[2]), "r"(a[3]), "r"(b[0]), "r"(b[1]));
}
__device__ __forceinline__ uint32_t pack_half(float a, float b) {
    __half2 h = __floats2half2_rn(a, b);
    return *(uint32_t*)&h;
}

// ======================= conversion kernels ================================
__global__ __launch_bounds__(256)
void split_kernel(const float* __restrict__ in, __half* __restrict__ hi,
                  __half* __restrict__ lo, int n4)
{
    int i = blockIdx.x * blockDim.x + threadIdx.x;
    if (i >= n4) return;
    float4 v = ((const float4*)in)[i];
    __half h0 = __float2half_rn(v.x), h1 = __float2half_rn(v.y);
    __half h2 = __float2half_rn(v.z), h3 = __float2half_rn(v.w);
    __half l0 = __float2half_rn(v.x - __half2float(h0));
    __half l1 = __float2half_rn(v.y - __half2float(h1));
    __half l2 = __float2half_rn(v.z - __half2float(h2));
    __half l3 = __float2half_rn(v.w - __half2float(h3));
    ushort4 hv = make_ushort4(*(unsigned short*)&h0, *(unsigned short*)&h1,
                              *(unsigned short*)&h2, *(unsigned short*)&h3);
    ushort4 lv = make_ushort4(*(unsigned short*)&l0, *(unsigned short*)&l1,
                              *(unsigned short*)&l2, *(unsigned short*)&l3);
    ((ushort4*)hi)[i] = hv;
    ((ushort4*)lo)[i] = lv;
}

// Merged QKV weight transpose: z selects {wq, wk, wv}; writes into g_wqkvt.
__global__ __launch_bounds__(256)
void transpose_qkv_kernel(const float* __restrict__ wq, const float* __restrict__ wk,
                          const float* __restrict__ wv)
{
    __shared__ float t[32][33];
    const float* W;
    int N, rowOff;
    if (blockIdx.z == 0)      { W = wq; N = DIM;   rowOff = 0; }
    else if (blockIdx.z == 1) { W = wk; N = KVDIM; rowOff = DIM; }
    else                      { W = wv; N = KVDIM; rowOff = DIM + KVDIM; }
    int n0 = blockIdx.x * 32, k0 = blockIdx.y * 32;
    if (n0 >= N) return;
    int tx = threadIdx.x & 31, ty = threadIdx.x >> 5;
#pragma unroll
    for (int i = 0; i < 4; i++)
        t[ty + i * 8][tx] = W[(size_t)(k0 + ty + i * 8) * N + n0 + tx];
    __syncthreads();
#pragma unroll
    for (int i = 0; i < 4; i++)
        g_wqkvt[(size_t)(rowOff + n0 + ty + i * 8) * KTOT + k0 + tx] =
            __float2half_rn(t[tx][ty + i * 8]);
}

// W[K][N] fp32 -> T[N][K] single fp16 (transpose) — for wo
__global__ __launch_bounds__(256)
void transpose_half_kernel(const float* __restrict__ W, __half* __restrict__ T,
                           int K, int N)
{
    __shared__ float t[32][33];
    int n0 = blockIdx.x * 32, k0 = blockIdx.y * 32;
    int tx = threadIdx.x & 31, ty = threadIdx.x >> 5;
#pragma unroll
    for (int i = 0; i < 4; i++)
        t[ty + i * 8][tx] = W[(size_t)(k0 + ty + i * 8) * N + n0 + tx];
    __syncthreads();
#pragma unroll
    for (int i = 0; i < 4; i++)
        T[(size_t)(n0 + ty + i * 8) * K + k0 + tx] = __float2half_rn(t[tx][ty + i * 8]);
}

// ======================= mma.sync GEMM (fp16 2-product) ====================
// C = (Ahi+Alo)[M,K] @ B[N,K]^T, fp32 acc. BM=BN=128, BK=32, 3-stage
// cp.async pipeline (wait_group 1), 256 thr, warps 4x2, warp tile 32x64.
// Prefetch issued mid-iteration (between k16 halves) to hide LDGSTS issue.
// MODE 0: fp32 C out (O projection).  MODE 1: fused QKV, per-CTA dispatch.
#define GSTRIDE  40
#define GS_MAT   (128 * GSTRIDE * 2)        // 10240 B
#define GS_STAGE (3 * GS_MAT)               // 30720 B: Ahi|Alo|B
#define GSTAGES  3
#define GEMM_SMEM_BYTES (GSTAGES * GS_STAGE)  // 92160

template<int MODE>
__global__ __launch_bounds__(256, 2)
void gemm_mma(const __half* __restrict__ Ahi, const __half* __restrict__ Alo,
              const __half* __restrict__ B,
              float* __restrict__ C,
              const float* __restrict__ fcos, const float* __restrict__ fsin)
{
    extern __shared__ char smem[];
    const uint32_t sbase = smem_u32(smem);
    const int tid  = threadIdx.x;
    const int lane = tid & 31;
    const int wid  = tid >> 5;
    const int wm   = wid & 3;
    const int wn   = wid >> 2;
    const int rowBase = blockIdx.y * 128;
    const int colBase = blockIdx.x * 128;

    auto prefetch = [&](int slot, int k0) {
        uint32_t st = sbase + (uint32_t)slot * GS_STAGE;
#pragma unroll
        for (int c = 0; c < 2; c++) {
            int ch  = tid + c * 256;          // 0..511
            int row = ch >> 2;                // 0..127
            int kc  = (ch & 3) * 8;           // 0,8,16,24
            uint32_t sm = (uint32_t)(row * GSTRIDE + kc) * 2;
            size_t ga = (size_t)(rowBase + row) * KTOT + k0 + kc;
            size_t gb = (size_t)(colBase + row) * KTOT + k0 + kc;
            CP_ASYNC16(st + 0 * GS_MAT + sm, Ahi + ga);
            CP_ASYNC16(st + 1 * GS_MAT + sm, Alo + ga);
            CP_ASYNC16(st + 2 * GS_MAT + sm, B   + gb);
        }
        CP_COMMIT();
    };

    float acc[2][8][4];
#pragma unroll
    for (int mi = 0; mi < 2; mi++)
#pragma unroll
        for (int ni = 0; ni < 8; ni++)
#pragma unroll
            for (int r = 0; r < 4; r++) acc[mi][ni][r] = 0.0f;

    const int am  = (lane & 7) + ((lane >> 3) & 1) * 8;
    const int ak  = (lane >> 4) * 8;
    const int bn4 = (lane & 7) + ((lane >> 4) & 1) * 8;
    const int bk4 = ((lane >> 3) & 1) * 8;

    prefetch(0, 0);
    prefetch(1, 32);

    int slot = 0;
    for (int i = 0; i < NK; i++) {
        CP_WAIT1();
        __syncthreads();

        const uint32_t st   = sbase + (uint32_t)slot * GS_STAGE;
        const uint32_t aHiB = st, aLoB = st + GS_MAT, bB = st + 2 * GS_MAT;
        slot = (slot + 1 == 3) ? 0 : slot + 1;

#pragma unroll
        for (int ks = 0; ks < 32; ks += 16) {
            uint32_t aHi[2][4], aLo[2][4];
#pragma unroll
            for (int mi = 0; mi < 2; mi++) {
                uint32_t off = (uint32_t)((wm * 32 + mi * 16 + am) * GSTRIDE + ks + ak) * 2;
                ldsm_x4(aHi[mi], aHiB + off);
                ldsm_x4(aLo[mi], aLoB + off);
            }
#pragma unroll
            for (int ni2 = 0; ni2 < 4; ni2++) {
                uint32_t boff = (uint32_t)((wn * 64 + ni2 * 16 + bn4) * GSTRIDE + ks + bk4) * 2;
                uint32_t bh[4];
                ldsm_x4(bh, bB + boff);
#pragma unroll
                for (int mi = 0; mi < 2; mi++) {
                    mma16816h(acc[mi][2 * ni2],     aHi[mi], bh);
                    mma16816h(acc[mi][2 * ni2 + 1], aHi[mi], bh + 2);
                    mma16816h(acc[mi][2 * ni2],     aLo[mi], bh);
                    mma16816h(acc[mi][2 * ni2 + 1], aLo[mi], bh + 2);
                }
            }
            // mid-iteration prefetch: hides LDGSTS issue behind MMA work
            if (ks == 0) {
                if (i + 2 < NK) prefetch((i + 2) % 3, (i + 2) * 32);
                else            CP_COMMIT();   // keep group-count invariant
            }
        }
        // no bottom barrier: prefetch targets a stage whose readers all
        // passed a later top barrier.
    }

    // ---- epilogue ----
    const int qrow = lane >> 2;
    const int qcol = (lane & 3) * 2;

    int region = 0, Nout = DIM, colOff = colBase;    // MODE 1 dispatch
    if (MODE == 1) {
        if (colBase < DIM)              { region = 0; Nout = DIM;   colOff = colBase; }
        else if (colBase < DIM + KVDIM) { region = 1; Nout = KVDIM; colOff = colBase - DIM; }
        else                            { region = 2; Nout = KVDIM; colOff = colBase - DIM - KVDIM; }
    }
    const float osc = 0.08838834764831844f;          // 1/sqrt(128), Q only

#pragma unroll
    for (int mi = 0; mi < 2; mi++) {
#pragma unroll
        for (int half = 0; half < 2; half++) {
            int r = rowBase + wm * 32 + mi * 16 + qrow + half * 8;
#pragma unroll
            for (int ni = 0; ni < 8; ni++) {
                int n_g = colOff + wn * 64 + ni * 8 + qcol;
                float c0 = acc[mi][ni][half * 2];
                float c1 = acc[mi][ni][half * 2 + 1];
                if (MODE == 0) {
                    *(float2*)&C[(size_t)r * DIM + n_g] = make_float2(c0, c1);
                } else {
                    float ox = c0, oy = c1;
                    if (region < 2) {                 // rope for Q and K
                        int d = (n_g & (HD - 1)) >> 1;
                        float fc = fcos[r * (HD / 2) + d];
                        float fs = fsin[r * (HD / 2) + d];
                        ox = c0 * fc - c1 * fs;
                        oy = c0 * fs + c1 * fc;
                    }
                    size_t o = (size_t)r * Nout + n_g;
                    if (region == 0) {                // Q: scale + split
                        ox *= osc; oy *= osc;
                        __half h0 = __float2half_rn(ox);
                        __half h1 = __float2half_rn(oy);
                        *(uint32_t*)&g_qhi[o] = pack_half(__half2float(h0), __half2float(h1));
                        *(uint32_t*)&g_qlo[o] = pack_half(ox - __half2float(h0),
                                                          oy - __half2float(h1));
                    } else if (region == 1) {         // K: single fp16
                        *(uint32_t*)&g_k[o] = pack_half(ox, oy);
                    } else {                          // V: single fp16
                        *(uint32_t*)&g_v[o] = pack_half(ox, oy);
                    }
                }
            }
        }
    }
}

// ======================= flash attention (fp16 2-product) ==================
// BM=64 q rows (4 warps x m16), BN=64 keys/tile, 128 threads, 2 CTAs/SM.
#define FPAD 136
#define FQ_BYTES   (64 * FPAD * 2)         // 17408 (per Q split-matrix)
#define FT_BYTES   (64 * FPAD * 2)         // 17408
#define FKV_BYTES  (2 * FT_BYTES)          // 34816: K | V
#define FLASH_SMEM (2 * FQ_BYTES + 2 * FKV_BYTES)   // 104448

__global__ __launch_bounds__(128, 2)
void flash_mma(const __half* __restrict__ qhi, const __half* __restrict__ qlo,
               const __half* __restrict__ k,  const __half* __restrict__ v,
               __half* __restrict__ atthi, __half* __restrict__ attlo)
{
    extern __shared__ char smem[];
    const uint32_t sbase = smem_u32(smem);
    const int tid  = threadIdx.x;
    const int lane = tid & 31;
    const int w    = tid >> 5;            // 4 warps: rows w*16..w*16+15
    const int qt   = gridDim.x - 1 - blockIdx.x;   // big tiles first
    const int head = blockIdx.y;
    const int kvh  = head >> 2;
    const int qbase = qt * 64;
    const int ktmax = qt;

    const uint32_t QHI = sbase;
    const uint32_t QLO = sbase + FQ_BYTES;
    const uint32_t KVB = sbase + 2 * FQ_BYTES;

#pragma unroll
    for (int t = 0; t < 16; t++) {
        int c = tid + t * 128;            // 0..2047
        int arr = c >> 10;                // 0=hi, 1=lo
        int rem = c & 1023;
        int row = rem >> 4;               // 0..63
        int ch  = rem & 15;
        const __half* src = arr ? qlo : qhi;
        uint32_t dst = (arr ? QLO : QHI) + (uint32_t)(row * FPAD + ch * 8) * 2;
        CP_ASYNC16(dst, src + (size_t)(qbase + row) * DIM + head * HD + ch * 8);
    }
    auto load_kv = [&](int buf, int kt) {
        const int kbase = kt * 64;
        uint32_t base = KVB + (uint32_t)buf * FKV_BYTES;
#pragma unroll
        for (int t = 0; t < 16; t++) {
            int c = tid + t * 128;        // 0..2047
            int arr = c >> 10;            // 0=K, 1=V
            int rem = c & 1023;
            int row = rem >> 4;
            int ch  = rem & 15;
            const __half* src = arr ? v : k;
            uint32_t dst = base + (uint32_t)arr * FT_BYTES + (uint32_t)(row * FPAD + ch * 8) * 2;
            CP_ASYNC16(dst, src + (size_t)(kbase + row) * KVDIM + kvh * HD + ch * 8);
        }
        CP_COMMIT();
    };
    load_kv(0, 0);   // one commit covering Q + tile 0

    const int am  = (lane & 7) + ((lane >> 3) & 1) * 8;
    const int ak  = (lane >> 4) * 8;
    const int kn4 = (lane & 7) + ((lane >> 4) & 1) * 8;
    const int kk4 = ((lane >> 3) & 1) * 8;
    const int vrow = ((lane >> 3) & 1) * 8 + (lane & 7);
    const int vcol = ((lane >> 4) & 1) * 8;
    const int qrow = lane >> 2;
    const int qcol = (lane & 3) * 2;

    float O[16][4];
#pragma unroll
    for (int ni = 0; ni < 16; ni++)
#pragma unroll
        for (int r = 0; r < 4; r++) O[ni][r] = 0.0f;
    float m0 = -1e30f, m1 = -1e30f, l0 = 0.0f, l1 = 0.0f;

    for (int kt = 0; kt <= ktmax; kt++) {
        CP_WAIT0();
        __syncthreads();
        if (kt + 1 <= ktmax) load_kv((kt + 1) & 1, kt + 1);

        const uint32_t base = KVB + (uint32_t)(kt & 1) * FKV_BYTES;
        const uint32_t KB = base, VB = base + FT_BYTES;

        // ---- S = (Qhi+Qlo) K^T ----
        float S[8][4];
#pragma unroll
        for (int j = 0; j < 8; j++)
#pragma unroll
            for (int r = 0; r < 4; r++) S[j][r] = 0.0f;

#pragma unroll
        for (int ks = 0; ks < 8; ks++) {
            uint32_t qh[4], ql[4];
            uint32_t qoff = (uint32_t)((w * 16 + am) * FPAD + ks * 16 + ak) * 2;
            ldsm_x4(qh, QHI + qoff);
            ldsm_x4(ql, QLO + qoff);
#pragma unroll
            for (int jp = 0; jp < 4; jp++) {
                uint32_t koff = (uint32_t)((jp * 16 + kn4) * FPAD + ks * 16 + kk4) * 2;
                uint32_t kh[4];
                ldsm_x4(kh, KB + koff);
                mma16816h(S[2 * jp],     qh, kh);
                mma16816h(S[2 * jp + 1], qh, kh + 2);
                mma16816h(S[2 * jp],     ql, kh);
                mma16816h(S[2 * jp + 1], ql, kh + 2);
            }
        }

        if (kt == qt) {                    // diagonal tile only
            const int kbase = kt * 64;
            int gq0 = qbase + w * 16 + qrow;
            int gq1 = gq0 + 8;
#pragma unroll
            for (int j = 0; j < 8; j++) {
                int gk = kbase + j * 8 + qcol;
                if (gk     > gq0) S[j][0] = -1e30f;
                if (gk + 1 > gq0) S[j][1] = -1e30f;
                if (gk     > gq1) S[j][2] = -1e30f;
                if (gk + 1 > gq1) S[j][3] = -1e30f;
            }
        }

        float mx0 = -1e30f, mx1 = -1e30f;
#pragma unroll
        for (int j = 0; j < 8; j++) {
            mx0 = fmaxf(mx0, fmaxf(S[j][0], S[j][1]));
            mx1 = fmaxf(mx1, fmaxf(S[j][2], S[j][3]));
        }
        mx0 = fmaxf(mx0, __shfl_xor_sync(0xffffffffu, mx0, 1));
        mx0 = fmaxf(mx0, __shfl_xor_sync(0xffffffffu, mx0, 2));
        mx1 = fmaxf(mx1, __shfl_xor_sync(0xffffffffu, mx1, 1));
        mx1 = fmaxf(mx1, __shfl_xor_sync(0xffffffffu, mx1, 2));

        float m0n = fmaxf(m0, mx0), m1n = fmaxf(m1, mx1);
        float a0 = __expf(m0 - m0n), a1 = __expf(m1 - m1n);
        float s0 = 0.0f, s1 = 0.0f;
#pragma unroll
        for (int j = 0; j < 8; j++) {
            S[j][0] = __expf(S[j][0] - m0n);
            S[j][1] = __expf(S[j][1] - m0n);
            S[j][2] = __expf(S[j][2] - m1n);
            S[j][3] = __expf(S[j][3] - m1n);
            s0 += S[j][0] + S[j][1];
            s1 += S[j][2] + S[j][3];
        }
        s0 += __shfl_xor_sync(0xffffffffu, s0, 1);
        s0 += __shfl_xor_sync(0xffffffffu, s0, 2);
        s1 += __shfl_xor_sync(0xffffffffu, s1, 1);
        s1 += __shfl_xor_sync(0xffffffffu, s1, 2);
        l0 = l0 * a0 + s0;  m0 = m0n;
        l1 = l1 * a1 + s1;  m1 = m1n;
#pragma unroll
        for (int ni = 0; ni < 16; ni++) {
            O[ni][0] *= a0; O[ni][1] *= a0;
            O[ni][2] *= a1; O[ni][3] *= a1;
        }

        // ---- O += (Phi+Plo) V ----
#pragma unroll
        for (int kt2 = 0; kt2 < 4; kt2++) {
            uint32_t ph[4], pl[4];
#pragma unroll
            for (int half = 0; half < 2; half++) {
                float p0 = S[2 * kt2 + half][0], p1 = S[2 * kt2 + half][1];
                float p2 = S[2 * kt2 + half][2], p3 = S[2 * kt2 + half][3];
                __half q0 = __float2half_rn(p0), q1 = __float2half_rn(p1);
                __half q2 = __float2half_rn(p2), q3 = __float2half_rn(p3);
                float h0 = __half2float(q0), h1 = __half2float(q1);
                float h2 = __half2float(q2), h3 = __half2float(q3);
                ph[half * 2 + 0] = pack_half(h0, h1);
                ph[half * 2 + 1] = pack_half(h2, h3);
                pl[half * 2 + 0] = pack_half(p0 - h0, p1 - h1);
                pl[half * 2 + 1] = pack_half(p2 - h2, p3 - h3);
            }
#pragma unroll
            for (int nip = 0; nip < 8; nip++) {
                uint32_t voff = (uint32_t)((kt2 * 16 + vrow) * FPAD + nip * 16 + vcol) * 2;
                uint32_t vh[4];
                ldsm_x4t(vh, VB + voff);
                mma16816h(O[2 * nip],     ph, vh);
                mma16816h(O[2 * nip + 1], ph, vh + 2);
                mma16816h(O[2 * nip],     pl, vh);
                mma16816h(O[2 * nip + 1], pl, vh + 2);
            }
        }
    }

    float inv0 = 1.0f / l0, inv1 = 1.0f / l1;
    int gq0 = qbase + w * 16 + qrow;
    int gq1 = gq0 + 8;
#pragma unroll
    for (int ni = 0; ni < 16; ni++) {
        int col = head * HD + ni * 8 + qcol;
        float o0 = O[ni][0] * inv0, o1 = O[ni][1] * inv0;
        float o2 = O[ni][2] * inv1, o3 = O[ni][3] * inv1;
        __half e0 = __float2half_rn(o0), e1 = __float2half_rn(o1);
        __half e2 = __float2half_rn(o2), e3 = __float2half_rn(o3);
        float h0 = __half2float(e0), h1 = __half2float(e1);
        float h2 = __half2float(e2), h3 = __half2float(e3);
        size_t p0 = (size_t)gq0 * DIM + col;
        size_t p1 = (size_t)gq1 * DIM + col;
        *(uint32_t*)&atthi[p0] = pack_half(h0, h1);
        *(uint32_t*)&attlo[p0] = pack_half(o0 - h0, o1 - h1);
        *(uint32_t*)&atthi[p1] = pack_half(h2, h3);
        *(uint32_t*)&attlo[p1] = pack_half(o2 - h2, o3 - h3);
    }
}

// ======================= launch ============================================
extern "C" void kernel_launch(void* const* d_in, const int* in_sizes, int n_in,
                              void* d_out, int out_size)
{
    const float* x    = (const float*)d_in[0];
    const float* wq   = (const float*)d_in[1];
    const float* wk   = (const float*)d_in[2];
    const float* wv   = (const float*)d_in[3];
    const float* wo   = (const float*)d_in[4];
    const float* fcos = (const float*)d_in[5];
    const float* fsin = (const float*)d_in[6];
    float* out = (float*)d_out;

    __half *xhi, *xlo, *wqkvt, *wot, *qhi, *qlo, *kk, *vv, *atthi, *attlo;
    cudaGetSymbolAddress((void**)&xhi,   g_xhi);
    cudaGetSymbolAddress((void**)&xlo,   g_xlo);
    cudaGetSymbolAddress((void**)&wqkvt, g_wqkvt);
    cudaGetSymbolAddress((void**)&wot,   g_wot);
    cudaGetSymbolAddress((void**)&qhi,   g_qhi);
    cudaGetSymbolAddress((void**)&qlo,   g_qlo);
    cudaGetSymbolAddress((void**)&kk,    g_k);
    cudaGetSymbolAddress((void**)&vv,    g_v);
    cudaGetSymbolAddress((void**)&atthi, g_atthi);
    cudaGetSymbolAddress((void**)&attlo, g_attlo);

    cudaFuncSetAttribute(gemm_mma<0>,
                         cudaFuncAttributeMaxDynamicSharedMemorySize, GEMM_SMEM_BYTES);
    cudaFuncSetAttribute(gemm_mma<1>,
                         cudaFuncAttributeMaxDynamicSharedMemorySize, GEMM_SMEM_BYTES);
    cudaFuncSetAttribute(flash_mma,
                         cudaFuncAttributeMaxDynamicSharedMemorySize, FLASH_SMEM);

    int n4x = S_LEN * DIM / 4;

    split_kernel<<<(n4x + 255) / 256, 256>>>(x, xhi, xlo, n4x);
    transpose_qkv_kernel<<<dim3(DIM / 32, DIM / 32, 3), 256>>>(wq, wk, wv);
    transpose_half_kernel<<<dim3(DIM / 32, DIM / 32), 256>>>(wo, wot, KTOT, DIM);

    gemm_mma<1><<<dim3(NQKV / 128, S_LEN / 128), 256, GEMM_SMEM_BYTES>>>(
        xhi, xlo, wqkvt, nullptr, fcos, fsin);

    flash_mma<<<dim3(S_LEN / 64, NH), 128, FLASH_SMEM>>>(
        qhi, qlo, kk, vv, atthi, attlo);

    gemm_mma<0><<<dim3(DIM / 128, S_LEN / 128), 256, GEMM_SMEM_BYTES>>>(
        atthi, attlo, wot, out, nullptr, nullptr);
}

// round 17
// speedup vs baseline: 1.2231x; 1.0048x over previous
#include <cuda_runtime.h>
#include <cuda_fp16.h>
#include <math.h>
#include <stdint.h>

#define DIM   4096
#define S_LEN 2048
#define HD    128
#define NH    32
#define NKV   8
#define KVDIM (NKV*HD)   // 1024
#define KTOT  4096
#define NK    (KTOT/32)  // 128
#define NQKV  (DIM + 2*KVDIM)   // 6144

// ======================= scratch globals ===================================
__device__ __half g_xhi [S_LEN * DIM];
__device__ __half g_xlo [S_LEN * DIM];
__device__ __half g_wqkvt[NQKV * KTOT];   // single fp16: wq^T | wk^T | wv^T
__device__ __half g_wot  [DIM * KTOT];
__device__ __half g_qhi [S_LEN * DIM];
__device__ __half g_qlo [S_LEN * DIM];
__device__ __half g_k   [S_LEN * KVDIM];
__device__ __half g_v   [S_LEN * KVDIM];
__device__ __half g_atthi[S_LEN * DIM];
__device__ __half g_attlo[S_LEN * DIM];

// ======================= asm helpers (sm_100-safe) =========================
__device__ __forceinline__ uint32_t smem_u32(const void* p) {
    uint32_t a;
    asm("{ .reg .u64 t; cvta.to.shared.u64 t, %1; cvt.u32.u64 %0, t; }"
        : "=r"(a) : "l"(p));
    return a;
}
#define CP_ASYNC16(dst, src) \
    asm volatile("cp.async.cg.shared.global [%0], [%1], 16;" :: "r"(dst), "l"(src))
#define CP_COMMIT()  asm volatile("cp.async.commit_group;" ::: "memory")
#define CP_WAIT0()   asm volatile("cp.async.wait_group 0;"  ::: "memory")
#define CP_WAIT1()   asm volatile("cp.async.wait_group 1;"  ::: "memory")

__device__ __forceinline__ void ldsm_x4(uint32_t* r, uint32_t addr) {
    asm volatile("ldmatrix.sync.aligned.m8n8.x4.shared.b16 {%0,%1,%2,%3}, [%4];"
                 : "=r"(r[0]), "=r"(r[1]), "=r"(r[2]), "=r"(r[3]) : "r"(addr));
}
__device__ __forceinline__ void ldsm_x4t(uint32_t* r, uint32_t addr) {
    asm volatile("ldmatrix.sync.aligned.m8n8.x4.trans.shared.b16 {%0,%1,%2,%3}, [%4];"
                 : "=r"(r[0]), "=r"(r[1]), "=r"(r[2]), "=r"(r[3]) : "r"(addr));
}
__device__ __forceinline__ void mma16816h(float* c, const uint32_t* a, const uint32_t* b) {
    asm volatile("mma.sync.aligned.m16n8k16.row.col.f32.f16.f16.f32 "
                 "{%0,%1,%2,%3}, {%4,%5,%6,%7}, {%8,%9}, {%0,%1,%2,%3};"
                 : "+f"(c[0]), "+f"(c[1]), "+f"(c[2]), "+f"(c[3])
                 : "r"(a[0]), "r"(a[1]), "r"(a[2]), "r"(a[3]), "r"(b[0]), "r"(b[1]));
}
__device__ __forceinline__ uint32_t pack_half(float a, float b) {
    __half2 h = __floats2half2_rn(a, b);
    return *(uint32_t*)&h;
}

// ======================= conversion kernels ================================
__global__ __launch_bounds__(256)
void split_kernel(const float* __restrict__ in, __half* __restrict__ hi,
                  __half* __restrict__ lo, int n4)
{
    int i = blockIdx.x * blockDim.x + threadIdx.x;
    if (i >= n4) return;
    float4 v = ((const float4*)in)[i];
    __half h0 = __float2half_rn(v.x), h1 = __float2half_rn(v.y);
    __half h2 = __float2half_rn(v.z), h3 = __float2half_rn(v.w);
    __half l0 = __float2half_rn(v.x - __half2float(h0));
    __half l1 = __float2half_rn(v.y - __half2float(h1));
    __half l2 = __float2half_rn(v.z - __half2float(h2));
    __half l3 = __float2half_rn(v.w - __half2float(h3));
    ushort4 hv = make_ushort4(*(unsigned short*)&h0, *(unsigned short*)&h1,
                              *(unsigned short*)&h2, *(unsigned short*)&h3);
    ushort4 lv = make_ushort4(*(unsigned short*)&l0, *(unsigned short*)&l1,
                              *(unsigned short*)&l2, *(unsigned short*)&l3);
    ((ushort4*)hi)[i] = hv;
    ((ushort4*)lo)[i] = lv;
}

// Merged QKV weight transpose: z selects {wq, wk, wv}; writes into g_wqkvt.
__global__ __launch_bounds__(256)
void transpose_qkv_kernel(const float* __restrict__ wq, const float* __restrict__ wk,
                          const float* __restrict__ wv)
{
    __shared__ float t[32][33];
    const float* W;
    int N, rowOff;
    if (blockIdx.z == 0)      { W = wq; N = DIM;   rowOff = 0; }
    else if (blockIdx.z == 1) { W = wk; N = KVDIM; rowOff = DIM; }
    else                      { W = wv; N = KVDIM; rowOff = DIM + KVDIM; }
    int n0 = blockIdx.x * 32, k0 = blockIdx.y * 32;
    if (n0 >= N) return;
    int tx = threadIdx.x & 31, ty = threadIdx.x >> 5;
#pragma unroll
    for (int i = 0; i < 4; i++)
        t[ty + i * 8][tx] = W[(size_t)(k0 + ty + i * 8) * N + n0 + tx];
    __syncthreads();
#pragma unroll
    for (int i = 0; i < 4; i++)
        g_wqkvt[(size_t)(rowOff + n0 + ty + i * 8) * KTOT + k0 + tx] =
            __float2half_rn(t[tx][ty + i * 8]);
}

// W[K][N] fp32 -> T[N][K] single fp16 (transpose) — for wo
__global__ __launch_bounds__(256)
void transpose_half_kernel(const float* __restrict__ W, __half* __restrict__ T,
                           int K, int N)
{
    __shared__ float t[32][33];
    int n0 = blockIdx.x * 32, k0 = blockIdx.y * 32;
    int tx = threadIdx.x & 31, ty = threadIdx.x >> 5;
#pragma unroll
    for (int i = 0; i < 4; i++)
        t[ty + i * 8][tx] = W[(size_t)(k0 + ty + i * 8) * N + n0 + tx];
    __syncthreads();
#pragma unroll
    for (int i = 0; i < 4; i++)
        T[(size_t)(n0 + ty + i * 8) * K + k0 + tx] = __float2half_rn(t[tx][ty + i * 8]);
}

// ======================= mma.sync GEMM (fp16 2-product) ====================
// C = (Ahi+Alo)[M,K] @ B[N,K]^T, fp32 acc. BM=BN=128, BK=32, 3-stage
// cp.async pipeline (wait_group 1), 256 thr, warps 4x2, warp tile 32x64.
// Prefetch issued mid-iteration (between k16 halves) to hide LDGSTS issue.
// MODE 0: fp32 C out (O projection).  MODE 1: fused QKV, per-CTA dispatch.
#define GSTRIDE  40
#define GS_MAT   (128 * GSTRIDE * 2)        // 10240 B
#define GS_STAGE (3 * GS_MAT)               // 30720 B: Ahi|Alo|B
#define GSTAGES  3
#define GEMM_SMEM_BYTES (GSTAGES * GS_STAGE)  // 92160

template<int MODE>
__global__ __launch_bounds__(256, 2)
void gemm_mma(const __half* __restrict__ Ahi, const __half* __restrict__ Alo,
              const __half* __restrict__ B,
              float* __restrict__ C,
              const float* __restrict__ fcos, const float* __restrict__ fsin)
{
    extern __shared__ char smem[];
    const uint32_t sbase = smem_u32(smem);
    const int tid  = threadIdx.x;
    const int lane = tid & 31;
    const int wid  = tid >> 5;
    const int wm   = wid & 3;
    const int wn   = wid >> 2;
    const int rowBase = blockIdx.y * 128;
    const int colBase = blockIdx.x * 128;

    auto prefetch = [&](int slot, int k0) {
        uint32_t st = sbase + (uint32_t)slot * GS_STAGE;
#pragma unroll
        for (int c = 0; c < 2; c++) {
            int ch  = tid + c * 256;          // 0..511
            int row = ch >> 2;                // 0..127
            int kc  = (ch & 3) * 8;           // 0,8,16,24
            uint32_t sm = (uint32_t)(row * GSTRIDE + kc) * 2;
            size_t ga = (size_t)(rowBase + row) * KTOT + k0 + kc;
            size_t gb = (size_t)(colBase + row) * KTOT + k0 + kc;
            CP_ASYNC16(st + 0 * GS_MAT + sm, Ahi + ga);
            CP_ASYNC16(st + 1 * GS_MAT + sm, Alo + ga);
            CP_ASYNC16(st + 2 * GS_MAT + sm, B   + gb);
        }
        CP_COMMIT();
    };

    float acc[2][8][4];
#pragma unroll
    for (int mi = 0; mi < 2; mi++)
#pragma unroll
        for (int ni = 0; ni < 8; ni++)
#pragma unroll
            for (int r = 0; r < 4; r++) acc[mi][ni][r] = 0.0f;

    const int am  = (lane & 7) + ((lane >> 3) & 1) * 8;
    const int ak  = (lane >> 4) * 8;
    const int bn4 = (lane & 7) + ((lane >> 4) & 1) * 8;
    const int bk4 = ((lane >> 3) & 1) * 8;

    prefetch(0, 0);
    prefetch(1, 32);

    int slot = 0;
    for (int i = 0; i < NK; i++) {
        CP_WAIT1();
        __syncthreads();

        const uint32_t st   = sbase + (uint32_t)slot * GS_STAGE;
        const uint32_t aHiB = st, aLoB = st + GS_MAT, bB = st + 2 * GS_MAT;
        slot = (slot + 1 == 3) ? 0 : slot + 1;

#pragma unroll
        for (int ks = 0; ks < 32; ks += 16) {
            uint32_t aHi[2][4], aLo[2][4];
#pragma unroll
            for (int mi = 0; mi < 2; mi++) {
                uint32_t off = (uint32_t)((wm * 32 + mi * 16 + am) * GSTRIDE + ks + ak) * 2;
                ldsm_x4(aHi[mi], aHiB + off);
                ldsm_x4(aLo[mi], aLoB + off);
            }
#pragma unroll
            for (int ni2 = 0; ni2 < 4; ni2++) {
                uint32_t boff = (uint32_t)((wn * 64 + ni2 * 16 + bn4) * GSTRIDE + ks + bk4) * 2;
                uint32_t bh[4];
                ldsm_x4(bh, bB + boff);
#pragma unroll
                for (int mi = 0; mi < 2; mi++) {
                    mma16816h(acc[mi][2 * ni2],     aHi[mi], bh);
                    mma16816h(acc[mi][2 * ni2 + 1], aHi[mi], bh + 2);
                    mma16816h(acc[mi][2 * ni2],     aLo[mi], bh);
                    mma16816h(acc[mi][2 * ni2 + 1], aLo[mi], bh + 2);
                }
            }
            // mid-iteration prefetch: hides LDGSTS issue behind MMA work
            if (ks == 0) {
                if (i + 2 < NK) prefetch((i + 2) % 3, (i + 2) * 32);
                else            CP_COMMIT();   // keep group-count invariant
            }
        }
        // no bottom barrier: prefetch targets a stage whose readers all
        // passed a later top barrier.
    }

    // ---- epilogue ----
    const int qrow = lane >> 2;
    const int qcol = (lane & 3) * 2;

    int region = 0, Nout = DIM, colOff = colBase;    // MODE 1 dispatch
    if (MODE == 1) {
        if (colBase < DIM)              { region = 0; Nout = DIM;   colOff = colBase; }
        else if (colBase < DIM + KVDIM) { region = 1; Nout = KVDIM; colOff = colBase - DIM; }
        else                            { region = 2; Nout = KVDIM; colOff = colBase - DIM - KVDIM; }
    }
    const float osc = 0.08838834764831844f;          // 1/sqrt(128), Q only

#pragma unroll
    for (int mi = 0; mi < 2; mi++) {
#pragma unroll
        for (int half = 0; half < 2; half++) {
            int r = rowBase + wm * 32 + mi * 16 + qrow + half * 8;
#pragma unroll
            for (int ni = 0; ni < 8; ni++) {
                int n_g = colOff + wn * 64 + ni * 8 + qcol;
                float c0 = acc[mi][ni][half * 2];
                float c1 = acc[mi][ni][half * 2 + 1];
                if (MODE == 0) {
                    *(float2*)&C[(size_t)r * DIM + n_g] = make_float2(c0, c1);
                } else {
                    float ox = c0, oy = c1;
                    if (region < 2) {                 // rope for Q and K
                        int d = (n_g & (HD - 1)) >> 1;
                        float fc = fcos[r * (HD / 2) + d];
                        float fs = fsin[r * (HD / 2) + d];
                        ox = c0 * fc - c1 * fs;
                        oy = c0 * fs + c1 * fc;
                    }
                    size_t o = (size_t)r * Nout + n_g;
                    if (region == 0) {                // Q: scale + split
                        ox *= osc; oy *= osc;
                        __half h0 = __float2half_rn(ox);
                        __half h1 = __float2half_rn(oy);
                        *(uint32_t*)&g_qhi[o] = pack_half(__half2float(h0), __half2float(h1));
                        *(uint32_t*)&g_qlo[o] = pack_half(ox - __half2float(h0),
                                                          oy - __half2float(h1));
                    } else if (region == 1) {         // K: single fp16
                        *(uint32_t*)&g_k[o] = pack_half(ox, oy);
                    } else {                          // V: single fp16
                        *(uint32_t*)&g_v[o] = pack_half(ox, oy);
                    }
                }
            }
        }
    }
}

// ======================= flash attention (fp16 2-product) ==================
// BM=64 q rows (4 warps x m16), BN=64 keys/tile, 128 threads, 2 CTAs/SM.
// load_kv for tile kt+1 issued MID-COMPUTE (after ks==0 of the S-loop),
// same placement fix that unblocked the GEMM in R16.
#define FPAD 136
#define FQ_BYTES   (64 * FPAD * 2)         // 17408 (per Q split-matrix)
#define FT_BYTES   (64 * FPAD * 2)         // 17408
#define FKV_BYTES  (2 * FT_BYTES)          // 34816: K | V
#define FLASH_SMEM (2 * FQ_BYTES + 2 * FKV_BYTES)   // 104448

__global__ __launch_bounds__(128, 2)
void flash_mma(const __half* __restrict__ qhi, const __half* __restrict__ qlo,
               const __half* __restrict__ k,  const __half* __restrict__ v,
               __half* __restrict__ atthi, __half* __restrict__ attlo)
{
    extern __shared__ char smem[];
    const uint32_t sbase = smem_u32(smem);
    const int tid  = threadIdx.x;
    const int lane = tid & 31;
    const int w    = tid >> 5;            // 4 warps: rows w*16..w*16+15
    const int qt   = gridDim.x - 1 - blockIdx.x;   // big tiles first
    const int head = blockIdx.y;
    const int kvh  = head >> 2;
    const int qbase = qt * 64;
    const int ktmax = qt;

    const uint32_t QHI = sbase;
    const uint32_t QLO = sbase + FQ_BYTES;
    const uint32_t KVB = sbase + 2 * FQ_BYTES;

#pragma unroll
    for (int t = 0; t < 16; t++) {
        int c = tid + t * 128;            // 0..2047
        int arr = c >> 10;                // 0=hi, 1=lo
        int rem = c & 1023;
        int row = rem >> 4;               // 0..63
        int ch  = rem & 15;
        const __half* src = arr ? qlo : qhi;
        uint32_t dst = (arr ? QLO : QHI) + (uint32_t)(row * FPAD + ch * 8) * 2;
        CP_ASYNC16(dst, src + (size_t)(qbase + row) * DIM + head * HD + ch * 8);
    }
    auto load_kv = [&](int buf, int kt) {
        const int kbase = kt * 64;
        uint32_t base = KVB + (uint32_t)buf * FKV_BYTES;
#pragma unroll
        for (int t = 0; t < 16; t++) {
            int c = tid + t * 128;        // 0..2047
            int arr = c >> 10;            // 0=K, 1=V
            int rem = c & 1023;
            int row = rem >> 4;
            int ch  = rem & 15;
            const __half* src = arr ? v : k;
            uint32_t dst = base + (uint32_t)arr * FT_BYTES + (uint32_t)(row * FPAD + ch * 8) * 2;
            CP_ASYNC16(dst, src + (size_t)(kbase + row) * KVDIM + kvh * HD + ch * 8);
        }
        CP_COMMIT();
    };
    load_kv(0, 0);   // one commit covering Q + tile 0

    const int am  = (lane & 7) + ((lane >> 3) & 1) * 8;
    const int ak  = (lane >> 4) * 8;
    const int kn4 = (lane & 7) + ((lane >> 4) & 1) * 8;
    const int kk4 = ((lane >> 3) & 1) * 8;
    const int vrow = ((lane >> 3) & 1) * 8 + (lane & 7);
    const int vcol = ((lane >> 4) & 1) * 8;
    const int qrow = lane >> 2;
    const int qcol = (lane & 3) * 2;

    float O[16][4];
#pragma unroll
    for (int ni = 0; ni < 16; ni++)
#pragma unroll
        for (int r = 0; r < 4; r++) O[ni][r] = 0.0f;
    float m0 = -1e30f, m1 = -1e30f, l0 = 0.0f, l1 = 0.0f;

    for (int kt = 0; kt <= ktmax; kt++) {
        CP_WAIT0();
        __syncthreads();

        const uint32_t base = KVB + (uint32_t)(kt & 1) * FKV_BYTES;
        const uint32_t KB = base, VB = base + FT_BYTES;

        // ---- S = (Qhi+Qlo) K^T ----
        float S[8][4];
#pragma unroll
        for (int j = 0; j < 8; j++)
#pragma unroll
            for (int r = 0; r < 4; r++) S[j][r] = 0.0f;

#pragma unroll
        for (int ks = 0; ks < 8; ks++) {
            uint32_t qh[4], ql[4];
            uint32_t qoff = (uint32_t)((w * 16 + am) * FPAD + ks * 16 + ak) * 2;
            ldsm_x4(qh, QHI + qoff);
            ldsm_x4(ql, QLO + qoff);
#pragma unroll
            for (int jp = 0; jp < 4; jp++) {
                uint32_t koff = (uint32_t)((jp * 16 + kn4) * FPAD + ks * 16 + kk4) * 2;
                uint32_t kh[4];
                ldsm_x4(kh, KB + koff);
                mma16816h(S[2 * jp],     qh, kh);
                mma16816h(S[2 * jp + 1], qh, kh + 2);
                mma16816h(S[2 * jp],     ql, kh);
                mma16816h(S[2 * jp + 1], ql, kh + 2);
            }
            // mid-compute load of next kv tile (R16 placement fix):
            // safe — writes target the buffer whose last readers all passed
            // the barrier at the top of THIS iteration.
            if (ks == 0 && kt + 1 <= ktmax) load_kv((kt + 1) & 1, kt + 1);
        }

        if (kt == qt) {                    // diagonal tile only
            const int kbase = kt * 64;
            int gq0 = qbase + w * 16 + qrow;
            int gq1 = gq0 + 8;
#pragma unroll
            for (int j = 0; j < 8; j++) {
                int gk = kbase + j * 8 + qcol;
                if (gk     > gq0) S[j][0] = -1e30f;
                if (gk + 1 > gq0) S[j][1] = -1e30f;
                if (gk     > gq1) S[j][2] = -1e30f;
                if (gk + 1 > gq1) S[j][3] = -1e30f;
            }
        }

        float mx0 = -1e30f, mx1 = -1e30f;
#pragma unroll
        for (int j = 0; j < 8; j++) {
            mx0 = fmaxf(mx0, fmaxf(S[j][0], S[j][1]));
            mx1 = fmaxf(mx1, fmaxf(S[j][2], S[j][3]));
        }
        mx0 = fmaxf(mx0, __shfl_xor_sync(0xffffffffu, mx0, 1));
        mx0 = fmaxf(mx0, __shfl_xor_sync(0xffffffffu, mx0, 2));
        mx1 = fmaxf(mx1, __shfl_xor_sync(0xffffffffu, mx1, 1));
        mx1 = fmaxf(mx1, __shfl_xor_sync(0xffffffffu, mx1, 2));

        float m0n = fmaxf(m0, mx0), m1n = fmaxf(m1, mx1);
        float a0 = __expf(m0 - m0n), a1 = __expf(m1 - m1n);
        float s0 = 0.0f, s1 = 0.0f;
#pragma unroll
        for (int j = 0; j < 8; j++) {
            S[j][0] = __expf(S[j][0] - m0n);
            S[j][1] = __expf(S[j][1] - m0n);
            S[j][2] = __expf(S[j][2] - m1n);
            S[j][3] = __expf(S[j][3] - m1n);
            s0 += S[j][0] + S[j][1];
            s1 += S[j][2] + S[j][3];
        }
        s0 += __shfl_xor_sync(0xffffffffu, s0, 1);
        s0 += __shfl_xor_sync(0xffffffffu, s0, 2);
        s1 += __shfl_xor_sync(0xffffffffu, s1, 1);
        s1 += __shfl_xor_sync(0xffffffffu, s1, 2);
        l0 = l0 * a0 + s0;  m0 = m0n;
        l1 = l1 * a1 + s1;  m1 = m1n;
#pragma unroll
        for (int ni = 0; ni < 16; ni++) {
            O[ni][0] *= a0; O[ni][1] *= a0;
            O[ni][2] *= a1; O[ni][3] *= a1;
        }

        // ---- O += (Phi+Plo) V ----
#pragma unroll
        for (int kt2 = 0; kt2 < 4; kt2++) {
            uint32_t ph[4], pl[4];
#pragma unroll
            for (int half = 0; half < 2; half++) {
                float p0 = S[2 * kt2 + half][0], p1 = S[2 * kt2 + half][1];
                float p2 = S[2 * kt2 + half][2], p3 = S[2 * kt2 + half][3];
                __half q0 = __float2half_rn(p0), q1 = __float2half_rn(p1);
                __half q2 = __float2half_rn(p2), q3 = __float2half_rn(p3);
                float h0 = __half2float(q0), h1 = __half2float(q1);
                float h2 = __half2float(q2), h3 = __half2float(q3);
                ph[half * 2 + 0] = pack_half(h0, h1);
                ph[half * 2 + 1] = pack_half(h2, h3);
                pl[half * 2 + 0] = pack_half(p0 - h0, p1 - h1);
                pl[half * 2 + 1] = pack_half(p2 - h2, p3 - h3);
            }
#pragma unroll
            for (int nip = 0; nip < 8; nip++) {
                uint32_t voff = (uint32_t)((kt2 * 16 + vrow) * FPAD + nip * 16 + vcol) * 2;
                uint32_t vh[4];
                ldsm_x4t(vh, VB + voff);
                mma16816h(O[2 * nip],     ph, vh);
                mma16816h(O[2 * nip + 1], ph, vh + 2);
                mma16816h(O[2 * nip],     pl, vh);
                mma16816h(O[2 * nip + 1], pl, vh + 2);
            }
        }
    }

    float inv0 = 1.0f / l0, inv1 = 1.0f / l1;
    int gq0 = qbase + w * 16 + qrow;
    int gq1 = gq0 + 8;
#pragma unroll
    for (int ni = 0; ni < 16; ni++) {
        int col = head * HD + ni * 8 + qcol;
        float o0 = O[ni][0] * inv0, o1 = O[ni][1] * inv0;
        float o2 = O[ni][2] * inv1, o3 = O[ni][3] * inv1;
        __half e0 = __float2half_rn(o0), e1 = __float2half_rn(o1);
        __half e2 = __float2half_rn(o2), e3 = __float2half_rn(o3);
        float h0 = __half2float(e0), h1 = __half2float(e1);
        float h2 = __half2float(e2), h3 = __half2float(e3);
        size_t p0 = (size_t)gq0 * DIM + col;
        size_t p1 = (size_t)gq1 * DIM + col;
        *(uint32_t*)&atthi[p0] = pack_half(h0, h1);
        *(uint32_t*)&attlo[p0] = pack_half(o0 - h0, o1 - h1);
        *(uint32_t*)&atthi[p1] = pack_half(h2, h3);
        *(uint32_t*)&attlo[p1] = pack_half(o2 - h2, o3 - h3);
    }
}

// ======================= launch ============================================
extern "C" void kernel_launch(void* const* d_in, const int* in_sizes, int n_in,
                              void* d_out, int out_size)
{
    const float* x    = (const float*)d_in[0];
    const float* wq   = (const float*)d_in[1];
    const float* wk   = (const float*)d_in[2];
    const float* wv   = (const float*)d_in[3];
    const float* wo   = (const float*)d_in[4];
    const float* fcos = (const float*)d_in[5];
    const float* fsin = (const float*)d_in[6];
    float* out = (float*)d_out;

    __half *xhi, *xlo, *wqkvt, *wot, *qhi, *qlo, *kk, *vv, *atthi, *attlo;
    cudaGetSymbolAddress((void**)&xhi,   g_xhi);
    cudaGetSymbolAddress((void**)&xlo,   g_xlo);
    cudaGetSymbolAddress((void**)&wqkvt, g_wqkvt);
    cudaGetSymbolAddress((void**)&wot,   g_wot);
    cudaGetSymbolAddress((void**)&qhi,   g_qhi);
    cudaGetSymbolAddress((void**)&qlo,   g_qlo);
    cudaGetSymbolAddress((void**)&kk,    g_k);
    cudaGetSymbolAddress((void**)&vv,    g_v);
    cudaGetSymbolAddress((void**)&atthi, g_atthi);
    cudaGetSymbolAddress((void**)&attlo, g_attlo);

    cudaFuncSetAttribute(gemm_mma<0>,
                         cudaFuncAttributeMaxDynamicSharedMemorySize, GEMM_SMEM_BYTES);
    cudaFuncSetAttribute(gemm_mma<1>,
                         cudaFuncAttributeMaxDynamicSharedMemorySize, GEMM_SMEM_BYTES);
    cudaFuncSetAttribute(flash_mma,
                         cudaFuncAttributeMaxDynamicSharedMemorySize, FLASH_SMEM);

    int n4x = S_LEN * DIM / 4;

    split_kernel<<<(n4x + 255) / 256, 256>>>(x, xhi, xlo, n4x);
    transpose_qkv_kernel<<<dim3(DIM / 32, DIM / 32, 3), 256>>>(wq, wk, wv);
    transpose_half_kernel<<<dim3(DIM / 32, DIM / 32), 256>>>(wo, wot, KTOT, DIM);

    gemm_mma<1><<<dim3(NQKV / 128, S_LEN / 128), 256, GEMM_SMEM_BYTES>>>(
        xhi, xlo, wqkvt, nullptr, fcos, fsin);

    flash_mma<<<dim3(S_LEN / 64, NH), 128, FLASH_SMEM>>>(
        qhi, qlo, kk, vv, atthi, attlo);

    gemm_mma<0><<<dim3(DIM / 128, S_LEN / 128), 256, GEMM_SMEM_BYTES>>>(
        atthi, attlo, wot, out, nullptr, nullptr);
}